// round 7
// baseline (speedup 1.0000x reference)
#include <cuda_runtime.h>
#include <cuda_bf16.h>

#define B_    32
#define PRE_  2048
#define POST_ 2048
#define KSPL  32      // forward split-K factor
#define PT_A  256     // forward p-tile per block
#define PT_C  128     // K2 p-tile
#define QT_C  64      // K2 q-tile

// ---- static device scratch (no allocations allowed) -------------------------
__device__ float g_part[KSPL * B_ * POST_];   // split-K partials, 8 MB
__device__ float g_tqn[B_ * POST_];           // NEGATED updated post trace
__device__ float g_tp [B_ * PRE_];            // updated pre trace

// ---- Blackwell packed-fp32 helpers ------------------------------------------
__device__ __forceinline__ void fma2(unsigned long long& d,
                                     unsigned long long a,
                                     unsigned long long b) {
    asm("fma.rn.f32x2 %0, %1, %2, %0;" : "+l"(d) : "l"(a), "l"(b));
}
__device__ __forceinline__ unsigned long long pk2(float lo, float hi) {
    unsigned long long r;
    asm("mov.b64 %0, {%1, %2};" : "=l"(r) : "f"(lo), "f"(hi));
    return r;
}
__device__ __forceinline__ float2 upk2(unsigned long long v) {
    float2 r;
    asm("mov.b64 {%0, %1}, %2;" : "=f"(r.x), "=f"(r.y) : "l"(v));
    return r;
}

// =============================================================================
// kA: forward split-K partials of i = x @ W^T.
// grid (POST/PT_A, KSPL), 256 threads (8 warps x 32 lanes).
// Lane owns ONE p-column and ALL 32 b as 16 packed (b0,b1) f32x2 accumulators.
// Per kk: w = LDS.32 (distinct, 1 wavefront) -> pk2 (alu pipe) -> 16 FFMA2 with
// x b-pairs read as natural u64 broadcasts. fma pipe and crossbar balanced.
// =============================================================================
__global__ __launch_bounds__(256) void kA(const float* __restrict__ x,
                                          const float* __restrict__ W) {
    __shared__ float Wt[16][PT_A];   // [kk][p_local] transposed W tile
    __shared__ float xs[16][B_];     // [kk][b] x tile (b adjacent -> u64 pairs)

    const int tid  = threadIdx.x;
    const int p0   = blockIdx.x * PT_A;
    const int k0   = blockIdx.y * (PRE_ / KSPL);   // 64-wide k range

    unsigned long long acc[16];
#pragma unroll
    for (int j = 0; j < 16; ++j) acc[j] = 0ull;

#pragma unroll 1
    for (int c = 0; c < 4; ++c) {                  // 4 chunks of 16 k
        const int kb = k0 + c * 16;
        // stage W[p0+tid][kb..kb+15] transposed (4 x float4 per thread)
        {
            const float4* wsrc = reinterpret_cast<const float4*>(
                W + (size_t)(p0 + tid) * PRE_ + kb);
            float4 v0 = wsrc[0], v1 = wsrc[1], v2 = wsrc[2], v3 = wsrc[3];
            Wt[ 0][tid] = v0.x; Wt[ 1][tid] = v0.y; Wt[ 2][tid] = v0.z; Wt[ 3][tid] = v0.w;
            Wt[ 4][tid] = v1.x; Wt[ 5][tid] = v1.y; Wt[ 6][tid] = v1.z; Wt[ 7][tid] = v1.w;
            Wt[ 8][tid] = v2.x; Wt[ 9][tid] = v2.y; Wt[10][tid] = v2.z; Wt[11][tid] = v2.w;
            Wt[12][tid] = v3.x; Wt[13][tid] = v3.y; Wt[14][tid] = v3.z; Wt[15][tid] = v3.w;
        }
        // stage x[b][kb+kk] -> xs[kk][b]   (512 elems, 2 per thread)
        {
            int i0 = tid;        int b0 = i0 & 31, kk0 = i0 >> 5;
            int i1 = tid + 256;  int b1 = i1 & 31, kk1 = i1 >> 5;
            xs[kk0][b0] = x[b0 * PRE_ + kb + kk0];
            xs[kk1][b1] = x[b1 * PRE_ + kb + kk1];
        }
        __syncthreads();
#pragma unroll
        for (int kk = 0; kk < 16; ++kk) {
            float w = Wt[kk][tid];
            unsigned long long wp = pk2(w, w);
            const unsigned long long* xr =
                reinterpret_cast<const unsigned long long*>(&xs[kk][0]);
#pragma unroll
            for (int j = 0; j < 16; ++j) fma2(acc[j], xr[j], wp);
        }
        __syncthreads();
    }
    // epilogue: partials, coalesced STG.32 across lanes
    float* pp = g_part + (size_t)blockIdx.y * (B_ * POST_);
#pragma unroll
    for (int j = 0; j < 16; ++j) {
        float2 v = upk2(acc[j]);
        pp[(size_t)(2 * j + 0) * POST_ + p0 + tid] = v.x;
        pp[(size_t)(2 * j + 1) * POST_ + p0 + tid] = v.y;
    }
}

// =============================================================================
// kB: reduce split-K partials -> spike; update traces (tq stored NEGATED).
// (B*POST == B*PRE == 65536, one index space covers both trace updates.)
// =============================================================================
__global__ __launch_bounds__(256) void kB(const float* __restrict__ x,
                                          const float* __restrict__ tpre,
                                          const float* __restrict__ tpost,
                                          float* __restrict__ out_spike) {
    const int idx = blockIdx.x * 256 + threadIdx.x;
    float s = 0.0f;
#pragma unroll
    for (int k = 0; k < KSPL; ++k) s += g_part[(size_t)k * (B_ * POST_) + idx];
    float spike = (s >= 1.0f) ? 1.0f : 0.0f;
    out_spike[idx] = spike;
    g_tqn[idx] = -(0.5f * tpost[idx] + spike);   // -(tpost - tpost/2 + spike)
    g_tp [idx] =   0.5f * tpre [idx] + x[idx];   //   tpre  - tpre/2  + x
}

// =============================================================================
// kC: dw[p][q] = clip(W) * ( sum_b spike[b][p]*tp[b][q] + tqn[b][p]*x[b][q] )
// grid (POST/PT_C, PRE/QT_C), 256 threads. Warp lanes span p (128 = 32x4),
// warp id selects an 8-wide q group (uniform q per warp -> broadcast LDS).
// Thread tile 4p x 8q, f32x2 pairs along q. smem = 48 KB exactly.
// =============================================================================
__global__ __launch_bounds__(256) void kC(const float* __restrict__ x,
                                          const float* __restrict__ W,
                                          const float* __restrict__ spike,
                                          float* __restrict__ dw) {
    __shared__ float sp [B_][PT_C];   // spike[b][p]
    __shared__ float tqn[B_][PT_C];   // -tq  [b][p]
    __shared__ float tp [B_][QT_C];   // tp   [b][q]
    __shared__ float xs [B_][QT_C];   // x    [b][q]

    const int tid = threadIdx.x;
    const int p0 = blockIdx.x * PT_C, q0 = blockIdx.y * QT_C;
    const int lane = tid & 31, wq = tid >> 5;
    const int pbase = lane * 4;       // thread's 4 p
    const int qbase = wq * 8;         // warp's 8 q (uniform across lanes)

    // stage p-side (2 x 4096 elems) and q-side (2 x 2048 elems), coalesced
#pragma unroll
    for (int r = 0; r < 16; ++r) {
        int i = tid + r * 256; int b = i >> 7, e = i & 127;
        sp [b][e] = spike[b * POST_ + p0 + e];
        tqn[b][e] = g_tqn[b * POST_ + p0 + e];
    }
#pragma unroll
    for (int r = 0; r < 8; ++r) {
        int i = tid + r * 256; int b = i >> 6, e = i & 63;
        tp[b][e] = g_tp[b * PRE_ + q0 + e];
        xs[b][e] = x   [b * PRE_ + q0 + e];
    }
    __syncthreads();

    unsigned long long acc[4][4];     // [p_i][q_pair]
#pragma unroll
    for (int i = 0; i < 4; ++i)
#pragma unroll
        for (int j = 0; j < 4; ++j) acc[i][j] = 0ull;

#pragma unroll
    for (int b = 0; b < B_; ++b) {
        float4 s4 = *reinterpret_cast<const float4*>(&sp [b][pbase]);
        float4 t4 = *reinterpret_cast<const float4*>(&tqn[b][pbase]);
        const unsigned long long* tpp =
            reinterpret_cast<const unsigned long long*>(&tp[b][qbase]);  // 4 u64
        const unsigned long long* xpp =
            reinterpret_cast<const unsigned long long*>(&xs[b][qbase]);  // 4 u64
        unsigned long long sd[4], td[4];
        sd[0] = pk2(s4.x, s4.x); sd[1] = pk2(s4.y, s4.y);
        sd[2] = pk2(s4.z, s4.z); sd[3] = pk2(s4.w, s4.w);
        td[0] = pk2(t4.x, t4.x); td[1] = pk2(t4.y, t4.y);
        td[2] = pk2(t4.z, t4.z); td[3] = pk2(t4.w, t4.w);
#pragma unroll
        for (int i = 0; i < 4; ++i) {
            unsigned long long u0 = tpp[0], u1 = tpp[1], u2 = tpp[2], u3 = tpp[3];
            fma2(acc[i][0], u0, sd[i]); fma2(acc[i][1], u1, sd[i]);
            fma2(acc[i][2], u2, sd[i]); fma2(acc[i][3], u3, sd[i]);
            unsigned long long v0 = xpp[0], v1 = xpp[1], v2 = xpp[2], v3 = xpp[3];
            fma2(acc[i][0], v0, td[i]); fma2(acc[i][1], v1, td[i]);
            fma2(acc[i][2], v2, td[i]); fma2(acc[i][3], v3, td[i]);
        }
    }

    // epilogue: clip W, scale, store (32B contiguous per lane -> full sectors)
#pragma unroll
    for (int i = 0; i < 4; ++i) {
        const int p = p0 + pbase + i;
        const float* wr = W  + (size_t)p * PRE_ + q0 + qbase;
        float*       dr = dw + (size_t)p * PRE_ + q0 + qbase;
        float4 wa = *reinterpret_cast<const float4*>(wr);
        float4 wb = *reinterpret_cast<const float4*>(wr + 4);
        float2 a0 = upk2(acc[i][0]), a1 = upk2(acc[i][1]);
        float2 a2 = upk2(acc[i][2]), a3 = upk2(acc[i][3]);
        float4 o0, o1;
        o0.x = fminf(fmaxf(wa.x, -1.f), 1.f) * a0.x;
        o0.y = fminf(fmaxf(wa.y, -1.f), 1.f) * a0.y;
        o0.z = fminf(fmaxf(wa.z, -1.f), 1.f) * a1.x;
        o0.w = fminf(fmaxf(wa.w, -1.f), 1.f) * a1.y;
        o1.x = fminf(fmaxf(wb.x, -1.f), 1.f) * a2.x;
        o1.y = fminf(fmaxf(wb.y, -1.f), 1.f) * a2.y;
        o1.z = fminf(fmaxf(wb.z, -1.f), 1.f) * a3.x;
        o1.w = fminf(fmaxf(wb.w, -1.f), 1.f) * a3.y;
        *reinterpret_cast<float4*>(dr)     = o0;
        *reinterpret_cast<float4*>(dr + 4) = o1;
    }
}

// =============================================================================
extern "C" void kernel_launch(void* const* d_in, const int* in_sizes, int n_in,
                              void* d_out, int out_size) {
    const float* x     = (const float*)d_in[0];   // [32, 2048]
    const float* W     = (const float*)d_in[1];   // [2048, 2048]
    const float* tpre  = (const float*)d_in[2];   // [32, 2048]
    const float* tpost = (const float*)d_in[3];   // [32, 2048]
    float* out     = (float*)d_out;
    float* spike_o = out;                         // [32, 2048]
    float* dw_o    = out + B_ * POST_;            // [2048, 2048]

    kA<<<dim3(POST_ / PT_A, KSPL), 256>>>(x, W);
    kB<<<(B_ * POST_) / 256, 256>>>(x, tpre, tpost, spike_o);
    kC<<<dim3(POST_ / PT_C, PRE_ / QT_C), 256>>>(x, W, spike_o, dw_o);
}

// round 9
// speedup vs baseline: 1.5454x; 1.5454x over previous
#include <cuda_runtime.h>
#include <cuda_bf16.h>

#define B_    32
#define PRE_  2048
#define POST_ 2048
#define KSPL  16

typedef unsigned int u32;

// ---- static device scratch ---------------------------------------------------
__device__ float g_part[KSPL * B_ * POST_];            // fwd split-K partials (4 MB)
__device__ float g_tqn[B_ * POST_];                    // -(updated post trace)
__device__ float g_tp [B_ * PRE_];                     // updated pre trace
__device__ __align__(16) __nv_bfloat16 g_Apack[POST_ * 128];  // dw A operand (K-major)
__device__ __align__(16) __nv_bfloat16 g_Bpack[PRE_  * 128];  // dw B operand (K-major)

struct alignas(8) BV4 { __nv_bfloat16 v[4]; };

// ---- mma.sync m16n8k16 bf16 (sm_80+ PTX; valid on plain sm_103) --------------
__device__ __forceinline__ void mma16816(float* d, const u32* a, const u32* b) {
    asm volatile(
        "mma.sync.aligned.m16n8k16.row.col.f32.bf16.bf16.f32 "
        "{%0,%1,%2,%3}, {%4,%5,%6,%7}, {%8,%9}, {%0,%1,%2,%3};"
        : "+f"(d[0]), "+f"(d[1]), "+f"(d[2]), "+f"(d[3])
        : "r"(a[0]), "r"(a[1]), "r"(a[2]), "r"(a[3]), "r"(b[0]), "r"(b[1]));
}
__device__ __forceinline__ u32 pack_bf2(__nv_bfloat16 a, __nv_bfloat16 b) {
    __nv_bfloat162 t = __halves2bfloat162(a, b);
    return *reinterpret_cast<u32*>(&t);
}
__device__ __forceinline__ void split3(float w, __nv_bfloat16& h,
                                       __nv_bfloat16& m, __nv_bfloat16& l) {
    h = __float2bfloat16(w);
    float r1 = w - __bfloat162float(h);
    m = __float2bfloat16(r1);
    l = __float2bfloat16(r1 - __bfloat162float(m));
}

// =============================================================================
// kA: forward split-K partials of i = x @ W^T via HMMA.
// grid (POST/128, KSPL), 128 threads (4 warps). Warp w: p columns w*32..+31.
// K per CTA = 128, staged in 4 chunks of 32. W fp32 -> 3 bf16 splits on the fly.
// Fragments loaded as direct u32 LDS (K-contiguous pairs), conflict-free strides.
// =============================================================================
__global__ __launch_bounds__(128) void kA(const float* __restrict__ x,
                                          const float* __restrict__ W) {
    __shared__ __nv_bfloat16 Ws[3][128][40];   // [split][p_local][k] pad->40
    __shared__ __nv_bfloat16 xs[32][40];       // [b][k]

    const int tid = threadIdx.x, wid = tid >> 5, lane = tid & 31;
    const int gid = lane >> 2, tig = lane & 3;
    const int p0 = blockIdx.x * 128;
    const int k0 = blockIdx.y * (PRE_ / KSPL);

    float acc[2][4][4];   // [m-frag(b 0-15/16-31)][n-frag(8p)][reg]
#pragma unroll
    for (int i = 0; i < 2; ++i)
#pragma unroll
        for (int j = 0; j < 4; ++j)
#pragma unroll
            for (int r = 0; r < 4; ++r) acc[i][j][r] = 0.0f;

#pragma unroll 1
    for (int c = 0; c < 4; ++c) {
        const int kb = k0 + c * 32;
        // stage W row p0+tid, 32 k: fp32 -> 3 bf16 splits (paired u32 stores)
        {
            const float4* wr = reinterpret_cast<const float4*>(
                W + (size_t)(p0 + tid) * PRE_ + kb);
#pragma unroll
            for (int j = 0; j < 8; ++j) {
                float4 v = wr[j];
                __nv_bfloat16 h0, m0, l0, h1, m1, l1;
                split3(v.x, h0, m0, l0); split3(v.y, h1, m1, l1);
                *reinterpret_cast<u32*>(&Ws[0][tid][j * 4])     = pack_bf2(h0, h1);
                *reinterpret_cast<u32*>(&Ws[1][tid][j * 4])     = pack_bf2(m0, m1);
                *reinterpret_cast<u32*>(&Ws[2][tid][j * 4])     = pack_bf2(l0, l1);
                split3(v.z, h0, m0, l0); split3(v.w, h1, m1, l1);
                *reinterpret_cast<u32*>(&Ws[0][tid][j * 4 + 2]) = pack_bf2(h0, h1);
                *reinterpret_cast<u32*>(&Ws[1][tid][j * 4 + 2]) = pack_bf2(m0, m1);
                *reinterpret_cast<u32*>(&Ws[2][tid][j * 4 + 2]) = pack_bf2(l0, l1);
            }
        }
        // stage x tile 32 x 32 (exact in bf16)
#pragma unroll
        for (int r = 0; r < 8; ++r) {
            int u = tid + r * 128;
            int b = u >> 5, k = u & 31;
            xs[b][k] = __float2bfloat16(x[b * PRE_ + kb + k]);
        }
        __syncthreads();

#pragma unroll
        for (int ks = 0; ks < 2; ++ks) {
            const int kc = ks * 16 + tig * 2;
            u32 a[2][4];
#pragma unroll
            for (int mf = 0; mf < 2; ++mf) {
                const int r0 = mf * 16 + gid;
                a[mf][0] = *reinterpret_cast<const u32*>(&xs[r0    ][kc]);
                a[mf][1] = *reinterpret_cast<const u32*>(&xs[r0 + 8][kc]);
                a[mf][2] = *reinterpret_cast<const u32*>(&xs[r0    ][kc + 8]);
                a[mf][3] = *reinterpret_cast<const u32*>(&xs[r0 + 8][kc + 8]);
            }
#pragma unroll
            for (int s = 0; s < 3; ++s) {
#pragma unroll
                for (int nf = 0; nf < 4; ++nf) {
                    const int n = wid * 32 + nf * 8 + gid;
                    u32 b[2];
                    b[0] = *reinterpret_cast<const u32*>(&Ws[s][n][kc]);
                    b[1] = *reinterpret_cast<const u32*>(&Ws[s][n][kc + 8]);
                    mma16816(acc[0][nf], a[0], b);
                    mma16816(acc[1][nf], a[1], b);
                }
            }
        }
        __syncthreads();
    }
    // epilogue: partials g_part[split][b][p], float2 stores
    float* pp = g_part + (size_t)blockIdx.y * (B_ * POST_);
#pragma unroll
    for (int mf = 0; mf < 2; ++mf)
#pragma unroll
        for (int nf = 0; nf < 4; ++nf) {
            const int p = p0 + wid * 32 + nf * 8 + tig * 2;
            const int b = mf * 16 + gid;
            *reinterpret_cast<float2*>(&pp[(size_t)b * POST_ + p]) =
                make_float2(acc[mf][nf][0], acc[mf][nf][1]);
            *reinterpret_cast<float2*>(&pp[(size_t)(b + 8) * POST_ + p]) =
                make_float2(acc[mf][nf][2], acc[mf][nf][3]);
        }
}

// =============================================================================
// kB: reduce partials -> spike; trace updates (tq negated).
// =============================================================================
__global__ __launch_bounds__(256) void kB(const float* __restrict__ x,
                                          const float* __restrict__ tpre,
                                          const float* __restrict__ tpost,
                                          float* __restrict__ out_spike) {
    const int idx = blockIdx.x * 256 + threadIdx.x;
    float s = 0.0f;
#pragma unroll
    for (int k = 0; k < KSPL; ++k) s += g_part[(size_t)k * (B_ * POST_) + idx];
    float spike = (s >= 1.0f) ? 1.0f : 0.0f;
    out_spike[idx] = spike;
    g_tqn[idx] = -(0.5f * tpost[idx] + spike);
    g_tp [idx] =   0.5f * tpre [idx] + x[idx];
}

// =============================================================================
// kPack: K-major bf16 operand packs for the dw GEMM (K=128).
//  A[p][kk]: 0-31 & 32-63 = spike[b][p] ; 64-95 = hi(tqn) ; 96-127 = lo(tqn)
//  B[q][kk]: 0-31 = hi(tp) ; 32-63 = lo(tp) ; 64-95 & 96-127 = x[b][q]
// =============================================================================
__global__ __launch_bounds__(256) void kPack(const float* __restrict__ x,
                                             const float* __restrict__ spike) {
    __shared__ float s0[32][65], s1[32][65];
    const int tid = threadIdx.x;
    const int r0 = blockIdx.x * 64;
    const bool isA = (blockIdx.y == 0);
    const float* src0 = isA ? spike : g_tp;
    const float* src1 = isA ? g_tqn : x;

#pragma unroll
    for (int r = 0; r < 8; ++r) {
        int i = tid + r * 256;
        int b = i >> 6, j = i & 63;
        s0[b][j] = src0[b * 2048 + r0 + j];
        s1[b][j] = src1[b * 2048 + r0 + j];
    }
    __syncthreads();

    __nv_bfloat16* dst = isA ? g_Apack : g_Bpack;
#pragma unroll
    for (int r = 0; r < 8; ++r) {
        int u = tid + r * 256;
        int rr = u >> 5, c4 = u & 31;
        int kk0 = c4 * 4;
        int reg = c4 >> 3;            // 32-kk region
        int bs  = (c4 & 7) * 4;
        BV4 o;
#pragma unroll
        for (int t = 0; t < 4; ++t) {
            int b = bs + t;
            float v0 = s0[b][rr], v1 = s1[b][rr];
            __nv_bfloat16 out;
            if (isA) {
                if (reg < 2) out = __float2bfloat16(v0);
                else {
                    __nv_bfloat16 h = __float2bfloat16(v1);
                    out = (reg == 2) ? h
                                     : __float2bfloat16(v1 - __bfloat162float(h));
                }
            } else {
                if (reg >= 2) out = __float2bfloat16(v1);
                else {
                    __nv_bfloat16 h = __float2bfloat16(v0);
                    out = (reg == 0) ? h
                                     : __float2bfloat16(v0 - __bfloat162float(h));
                }
            }
            o.v[t] = out;
        }
        *reinterpret_cast<BV4*>(&dst[(size_t)(r0 + rr) * 128 + kk0]) = o;
    }
}

// =============================================================================
// kC: dw = clip(W) * (Apack @ Bpack^T), K=128 HMMA. grid (16,16), 256 thr.
// 8 warps as 2(p) x 4(q); warp tile 64p x 32q; thread frag stores float2.
// =============================================================================
#define KC_STRIDE 136
#define KC_SMEM   (2 * 128 * KC_STRIDE * 2)

__global__ __launch_bounds__(256) void kC(const float* __restrict__ W,
                                          float* __restrict__ dw) {
    extern __shared__ __nv_bfloat16 sm[];
    __nv_bfloat16 (*As)[KC_STRIDE] = reinterpret_cast<__nv_bfloat16(*)[KC_STRIDE]>(sm);
    __nv_bfloat16 (*Bs)[KC_STRIDE] =
        reinterpret_cast<__nv_bfloat16(*)[KC_STRIDE]>(sm + 128 * KC_STRIDE);

    const int tid = threadIdx.x, wid = tid >> 5, lane = tid & 31;
    const int gid = lane >> 2, tig = lane & 3;
    const int pw = wid >> 2, qw = wid & 3;
    const int p0 = blockIdx.x * 128, q0 = blockIdx.y * 128;

    // stage both 128x128 bf16 tiles (uint4 loads, 16B-aligned smem rows)
#pragma unroll
    for (int r = 0; r < 8; ++r) {
        int u = tid + r * 256;
        int row = u >> 4, c16 = u & 15;
        *reinterpret_cast<uint4*>(&As[row][c16 * 8]) =
            *reinterpret_cast<const uint4*>(&g_Apack[(size_t)(p0 + row) * 128 + c16 * 8]);
        *reinterpret_cast<uint4*>(&Bs[row][c16 * 8]) =
            *reinterpret_cast<const uint4*>(&g_Bpack[(size_t)(q0 + row) * 128 + c16 * 8]);
    }
    __syncthreads();

    float acc[4][4][4];   // [m-frag][n-frag][reg]
#pragma unroll
    for (int i = 0; i < 4; ++i)
#pragma unroll
        for (int j = 0; j < 4; ++j)
#pragma unroll
            for (int r = 0; r < 4; ++r) acc[i][j][r] = 0.0f;

#pragma unroll
    for (int kk = 0; kk < 8; ++kk) {
        const int kc = kk * 16 + tig * 2;
        u32 a[4][4];
#pragma unroll
        for (int mf = 0; mf < 4; ++mf) {
            const int r0 = pw * 64 + mf * 16 + gid;
            a[mf][0] = *reinterpret_cast<const u32*>(&As[r0    ][kc]);
            a[mf][1] = *reinterpret_cast<const u32*>(&As[r0 + 8][kc]);
            a[mf][2] = *reinterpret_cast<const u32*>(&As[r0    ][kc + 8]);
            a[mf][3] = *reinterpret_cast<const u32*>(&As[r0 + 8][kc + 8]);
        }
#pragma unroll
        for (int nf = 0; nf < 4; ++nf) {
            const int n = qw * 32 + nf * 8 + gid;
            u32 b[2];
            b[0] = *reinterpret_cast<const u32*>(&Bs[n][kc]);
            b[1] = *reinterpret_cast<const u32*>(&Bs[n][kc + 8]);
#pragma unroll
            for (int mf = 0; mf < 4; ++mf) mma16816(acc[mf][nf], a[mf], b);
        }
    }

    // epilogue: clip(W) * acc -> dw (float2 per thread per row)
#pragma unroll
    for (int mf = 0; mf < 4; ++mf)
#pragma unroll
        for (int nf = 0; nf < 4; ++nf) {
            const int p = p0 + pw * 64 + mf * 16 + gid;
            const int q = q0 + qw * 32 + nf * 8 + tig * 2;
            float2 w0 = *reinterpret_cast<const float2*>(&W[(size_t)p * PRE_ + q]);
            float2 w1 = *reinterpret_cast<const float2*>(&W[(size_t)(p + 8) * PRE_ + q]);
            float2 o0, o1;
            o0.x = fminf(fmaxf(w0.x, -1.f), 1.f) * acc[mf][nf][0];
            o0.y = fminf(fmaxf(w0.y, -1.f), 1.f) * acc[mf][nf][1];
            o1.x = fminf(fmaxf(w1.x, -1.f), 1.f) * acc[mf][nf][2];
            o1.y = fminf(fmaxf(w1.y, -1.f), 1.f) * acc[mf][nf][3];
            *reinterpret_cast<float2*>(&dw[(size_t)p * PRE_ + q])       = o0;
            *reinterpret_cast<float2*>(&dw[(size_t)(p + 8) * PRE_ + q]) = o1;
        }
}

// =============================================================================
extern "C" void kernel_launch(void* const* d_in, const int* in_sizes, int n_in,
                              void* d_out, int out_size) {
    const float* x     = (const float*)d_in[0];   // [32, 2048]
    const float* W     = (const float*)d_in[1];   // [2048, 2048]
    const float* tpre  = (const float*)d_in[2];   // [32, 2048]
    const float* tpost = (const float*)d_in[3];   // [32, 2048]
    float* out     = (float*)d_out;
    float* spike_o = out;                         // [32, 2048]
    float* dw_o    = out + B_ * POST_;            // [2048, 2048]

    cudaFuncSetAttribute(kC, cudaFuncAttributeMaxDynamicSharedMemorySize, KC_SMEM);

    kA<<<dim3(POST_ / 128, KSPL), 128>>>(x, W);
    kB<<<(B_ * POST_) / 256, 256>>>(x, tpre, tpost, spike_o);
    kPack<<<dim3(2048 / 64, 2), 256>>>(x, spike_o);
    kC<<<dim3(POST_ / 128, PRE_ / 128), 256, KC_SMEM>>>(W, dw_o);
}